// round 15
// baseline (speedup 1.0000x reference)
#include <cuda_runtime.h>
#include <math.h>
#include <float.h>

#define BB 16
#define TT 512
#define DD 512

typedef unsigned long long ull;
__device__ __forceinline__ ull umax64(ull a, ull b) { return a > b ? a : b; }
__device__ __forceinline__ ull umin64(ull a, ull b) { return a < b ? a : b; }
__device__ __forceinline__ float ex2f(float x) {
    float y; asm("ex2.approx.ftz.f32 %0, %1;" : "=f"(y) : "f"(x)); return y;
}

// ---------------- scratch (static __device__ — no allocations) ----------------
__device__ float g_xtr[BB * DD];                    // x_trans (before +b_lin)
__device__ int   g_done = 0;                        // last-block counter (reset each run)

// ---------------- fused: 4 series per block + last-block inline router ----------------
__global__ void __launch_bounds__(256, 6) k_fused(const float* __restrict__ x,
                                                  const float* __restrict__ W_trend,
                                                  const float* __restrict__ b_trend,
                                                  const float* __restrict__ W_lin,
                                                  const float* __restrict__ noise,
                                                  const float* __restrict__ W_r,
                                                  const float* __restrict__ b_r,
                                                  const float* __restrict__ W_noise,
                                                  const float* __restrict__ b_noise,
                                                  const float* __restrict__ b_lin,
                                                  float* __restrict__ out) {
    __shared__ __align__(16) float2 s_pp[2][1024];  // FFT ping-pong; buf1 = raw spectrum, later rem
    __shared__ float2 s_trig[512];      // {cos, sin}(2*pi*j/512)
    __shared__ __align__(16) float s_cse[4][548];   // extended cumsum: index i+16, i in [-16, 531]
    __shared__ int    s_wk[4][4];
    __shared__ float  s_wr[4][4], s_wi[4][4];
    __shared__ float  s_red[4][8];
    __shared__ int    s_last;

    int tid = threadIdx.x;
    int lane = tid & 31, w = tid >> 5;
    int bidx = blockIdx.x;
    int b  = bidx >> 7;                 // 128 blocks per batch (512/4)
    int d0 = (bidx & 127) << 2;

    // issue strided global loads first (latency hidden by trig below)
    const float* xp = x + ((size_t)b * TT + tid) * DD + d0;
    float4 v0 = *(const float4*)xp;
    float4 v1 = *(const float4*)(xp + (size_t)256 * DD);

    // trig table: one sincospif; second half via cos(pi+a) = -cos(a)
    {
        float s0, c0;
        sincospif((float)tid * (1.0f / 256.0f), &s0, &c0);
        s_trig[tid]       = make_float2(c0, s0);
        s_trig[tid + 256] = make_float2(-c0, -s0);
    }

    // x values for this thread's positions (t = tid, tid+256), all 4 series -> registers
    float xv[4][2];
    xv[0][0] = v0.x; xv[1][0] = v0.y; xv[2][0] = v0.z; xv[3][0] = v0.w;
    xv[0][1] = v1.x; xv[1][1] = v1.y; xv[2][1] = v1.z; xv[3][1] = v1.w;

    // pack fft0 = x(d0) + i x(d0+1), fft1 = x(d0+2) + i x(d0+3)
    s_pp[0][tid]             = make_float2(v0.x, v0.y);
    s_pp[0][tid + 256]       = make_float2(v1.x, v1.y);
    s_pp[0][512 + tid]       = make_float2(v0.z, v0.w);
    s_pp[0][512 + tid + 256] = make_float2(v1.z, v1.w);

    __syncthreads();
    // ---- radix-4 stage 0 (Ns = 1): all twiddles are (1,0) -> pure adds ----
    {
        int f = tid >> 7;
        int j = tid & 127;
        int base = f << 9;
        float2 a0 = s_pp[0][base + j];
        float2 a1 = s_pp[0][base + j + 128];
        float2 a2 = s_pp[0][base + j + 256];
        float2 a3 = s_pp[0][base + j + 384];
        float y0r = a0.x + a1.x + a2.x + a3.x, y0i = a0.y + a1.y + a2.y + a3.y;
        float y2r = a0.x - a1.x + a2.x - a3.x, y2i = a0.y - a1.y + a2.y - a3.y;
        float y1r = a0.x + a1.y - a2.x - a3.y, y1i = a0.y - a1.x - a2.y + a3.x;
        float y3r = a0.x - a1.y - a2.x + a3.y, y3i = a0.y + a1.x - a2.y - a3.x;
        int o = base + 4 * j;
        s_pp[1][o]     = make_float2(y0r, y0i);
        s_pp[1][o + 1] = make_float2(y1r, y1i);
        s_pp[1][o + 2] = make_float2(y2r, y2i);
        s_pp[1][o + 3] = make_float2(y3r, y3i);
    }
    int cur = 1;
    // ---- radix-4 stages 1..3 (Ns = 4,16,64) ----
    #pragma unroll
    for (int st = 1; st < 4; st++) {
        int Ns = 1 << (2 * st);
        int shiftm = 7 - 2 * st;         // twiddle idx = k * (128/Ns)
        __syncthreads();
        int f = tid >> 7;                // fft id
        int j = tid & 127;
        int k = j & (Ns - 1);
        int base = f << 9;
        float2 a0 = s_pp[cur][base + j];
        float2 a1 = s_pp[cur][base + j + 128];
        float2 a2 = s_pp[cur][base + j + 256];
        float2 a3 = s_pp[cur][base + j + 384];
        int m = k << shiftm;
        float2 w1 = s_trig[m], w2 = s_trig[2 * m], w3 = s_trig[3 * m];
        float t1r = w1.x * a1.x + w1.y * a1.y, t1i = w1.x * a1.y - w1.y * a1.x;
        float t2r = w2.x * a2.x + w2.y * a2.y, t2i = w2.x * a2.y - w2.y * a2.x;
        float t3r = w3.x * a3.x + w3.y * a3.y, t3i = w3.x * a3.y - w3.y * a3.x;
        float y0r = a0.x + t1r + t2r + t3r, y0i = a0.y + t1i + t2i + t3i;
        float y2r = a0.x - t1r + t2r - t3r, y2i = a0.y - t1i + t2i - t3i;
        float y1r = a0.x + t1i - t2r - t3i, y1i = a0.y - t1r - t2i + t3r;
        float y3r = a0.x - t1i - t2r + t3i, y3i = a0.y + t1r - t2i - t3r;
        int o = base + 4 * j - 3 * k;
        int nxt = cur ^ 1;
        s_pp[nxt][o]          = make_float2(y0r, y0i);
        s_pp[nxt][o + Ns]     = make_float2(y1r, y1i);
        s_pp[nxt][o + 2 * Ns] = make_float2(y2r, y2i);
        s_pp[nxt][o + 3 * Ns] = make_float2(y3r, y3i);
        cur = nxt;
    }
    // ---- final radix-2 stage (Ns = 256) -> raw spectrum lands in buf1 ----
    __syncthreads();
    {
        int k = tid;
        float2 wv = s_trig[k];
        int nxt = cur ^ 1;
        #pragma unroll
        for (int f = 0; f < 2; f++) {
            int base = f << 9;
            float2 a = s_pp[cur][base + k];
            float2 c = s_pp[cur][base + k + 256];
            float tr = wv.x * c.x + wv.y * c.y, ti = wv.x * c.y - wv.y * c.x;
            s_pp[nxt][base + k]       = make_float2(a.x + tr, a.y + ti);
            s_pp[nxt][base + k + 256] = make_float2(a.x - tr, a.y - ti);
        }
        cur = nxt;                        // final spectrum in buf 1
    }
    __syncthreads();

    // ---- warp top-4 per series (warps 0..3) directly on raw spectrum (no unpack phase)
    //      series s = w: fft f = w>>1, parity p = w&1.
    //      p==0: Xr=.5(Zr+Mr), Xi=.5(Zi-Mi);  p==1: Xr=.5(Zi+Mi), Xi=.5(Mr-Zr)
    if (w < 4) {
        const float2* Zb = &s_pp[1][(w >> 1) << 9];
        int par = w & 1;
        ull c0 = 0, c1 = 0, c2 = 0, c3 = 0;
        #pragma unroll
        for (int j = 0; j < 8; j++) {
            int k = lane + 32 * j;
            ull p;
            if (k == 0) p = 0ull;
            else {
                float2 Z = Zb[k], M = Zb[512 - k];
                float Xr, Xi;
                if (par == 0) { Xr = 0.5f * (Z.x + M.x); Xi = 0.5f * (Z.y - M.y); }
                else          { Xr = 0.5f * (Z.y + M.y); Xi = 0.5f * (M.x - Z.x); }
                float a = Xr * Xr + Xi * Xi;
                p = ((ull)__float_as_uint(a) << 32) | (ull)(511 - k);
            }
            ull t;
            t = umin64(c0, p); c0 = umax64(c0, p); p = t;
            t = umin64(c1, p); c1 = umax64(c1, p); p = t;
            t = umin64(c2, p); c2 = umax64(c2, p); p = t;
            c3 = umax64(c3, p);
        }
        #pragma unroll
        for (int off = 16; off; off >>= 1) {
            ull o0 = __shfl_xor_sync(0xffffffffu, c0, off);
            ull o1 = __shfl_xor_sync(0xffffffffu, c1, off);
            ull o2 = __shfl_xor_sync(0xffffffffu, c2, off);
            ull o3 = __shfl_xor_sync(0xffffffffu, c3, off);
            bool mf = c0 > o0;
            ull u0 = mf ? c0 : o0, u1 = mf ? c1 : o1, u2 = mf ? c2 : o2, u3 = mf ? c3 : o3;
            ull v0_ = mf ? o0 : c0, v1_ = mf ? o1 : c1, v2_ = mf ? o2 : c2, v3_ = mf ? o3 : c3;
            ull A0 = umax64(u0, v3_), A1 = umax64(u1, v2_);
            ull A2 = umax64(u2, v1_), A3 = umax64(u3, v0_);
            ull B0 = umax64(A0, A2), B2 = umin64(A0, A2);
            ull B1 = umax64(A1, A3), B3 = umin64(A1, A3);
            c0 = umax64(B0, B1); c1 = umin64(B0, B1);
            c2 = umax64(B2, B3); c3 = umin64(B2, B3);
        }
        if (lane == 0) {
            ull cc[4] = {c0, c1, c2, c3};
            #pragma unroll
            for (int r = 0; r < 4; r++) {
                int kk = 511 - (int)(cc[r] & 0xffffffffull);
                float2 Z = Zb[kk], M = Zb[512 - kk];
                float Xr, Xi;
                if (par == 0) { Xr = 0.5f * (Z.x + M.x); Xi = 0.5f * (Z.y - M.y); }
                else          { Xr = 0.5f * (Z.y + M.y); Xi = 0.5f * (M.x - Z.x); }
                s_wk[w][r] = kk; s_wr[w][r] = Xr; s_wi[w][r] = Xi;
            }
        }
    }
    __syncthreads();

    // ---- season + remainder with parity trick; rem overwrites buf1 ----
    float* remall = (float*)&s_pp[1][0];
    float remv[4][2];
    #pragma unroll
    for (int s = 0; s < 4; s++) {
        float se0 = 0.f, se1 = 0.f;
        #pragma unroll
        for (int j = 0; j < 4; j++) {
            int   kk = s_wk[s][j];
            float rr = s_wr[s][j], ii = s_wi[s][j];
            float2 T = s_trig[(kk * tid) & 511];
            float term = rr * T.x - ii * T.y;
            se0 += term;
            se1 += (kk & 1) ? -term : term;
        }
        float rv0 = xv[s][0] - se0 * (2.0f / 512.0f);
        float rv1 = xv[s][1] - se1 * (2.0f / 512.0f);
        remv[s][0] = rv0; remv[s][1] = rv1;
        float* remp = remall + s * 512;
        remp[tid] = rv0;
        remp[tid + 256] = rv1;
    }
    __syncthreads();

    // ---- 4 parallel cumsums, float4 pass-based scan (4 passes of 128) ----
    if (w < 4) {
        const float4* rm4 = (const float4*)(remall + w * 512);
        float* cse = s_cse[w];
        float offset = 0.f;
        #pragma unroll
        for (int i = 0; i < 4; i++) {
            float4 v = rm4[i * 32 + lane];
            float sv = v.x + v.y + v.z + v.w;
            float inc = sv;
            #pragma unroll
            for (int sft = 1; sft < 32; sft <<= 1) {
                float u = __shfl_up_sync(0xffffffffu, inc, sft);
                if (lane >= sft) inc += u;
            }
            float excl = offset + (inc - sv);
            float4 o4;
            o4.x = excl;
            o4.y = excl + v.x;
            o4.z = o4.y + v.y;
            o4.w = o4.z + v.z;
            ((float4*)(cse + 16))[i * 32 + lane] = o4;
            offset += __shfl_sync(0xffffffffu, inc, 31);
        }
        if (lane == 31) cse[16 + 512] = offset;             // total
        if (lane < 16) {
            float rem0 = remall[w * 512], remL = remall[w * 512 + 511];
            cse[lane] = (float)(lane - 16) * rem0;                      // i = lane-16
            cse[16 + 513 + lane] = offset + (float)(lane + 1) * remL;   // i = 513+lane
        }
    }
    __syncthreads();

    // ---- trend + W_lin reduce, 4 series (rem & x from registers) ----
    const float LOG2E = 1.44269504f;
    float Wt2[6], bt2[6];
    #pragma unroll
    for (int j = 0; j < 6; j++) { Wt2[j] = W_trend[j] * LOG2E; bt2[j] = b_trend[j] * LOG2E; }
    const int   koff[6] = {2, 4, 6, 8, 12, 16};        // k/2
    const float inv[6] = {0.25f, 0.125f, 1.f / 12.f, 0.0625f, 1.f / 24.f, 0.03125f};
    float wl0 = W_lin[tid], wl1 = W_lin[tid + 256];

    float accv[4];
    #pragma unroll
    for (int s = 0; s < 4; s++) {
        const float* cse = s_cse[s] + 16;
        float acc = 0.f;
        #pragma unroll
        for (int tt = 0; tt < 2; tt++) {
            int t = tid + tt * 256;
            float rem = remv[s][tt];
            const float* cp = cse + t;
            float es = 0.f, ws = 0.f;
            #pragma unroll
            for (int j = 0; j < 6; j++) {
                float ssum = cp[koff[j]] - cp[-koff[j]];
                float e = ex2f(fmaf(rem, Wt2[j], bt2[j]));
                es += e;
                ws = fmaf(e, ssum * inv[j], ws);
            }
            float trend = __fdividef(ws, es);
            float xsum = 2.0f * xv[s][tt] - rem + trend;
            acc = fmaf(xsum, (tt ? wl1 : wl0), acc);
        }
        accv[s] = acc;
    }

    #pragma unroll
    for (int o = 16; o > 0; o >>= 1) {
        accv[0] += __shfl_down_sync(0xffffffffu, accv[0], o);
        accv[1] += __shfl_down_sync(0xffffffffu, accv[1], o);
        accv[2] += __shfl_down_sync(0xffffffffu, accv[2], o);
        accv[3] += __shfl_down_sync(0xffffffffu, accv[3], o);
    }
    if (lane == 0) {
        s_red[0][w] = accv[0]; s_red[1][w] = accv[1];
        s_red[2][w] = accv[2]; s_red[3][w] = accv[3];
    }
    __syncthreads();
    if (tid < 4) {
        float s = 0.f;
        #pragma unroll
        for (int ww = 0; ww < 8; ww++) s += s_red[tid][ww];
        g_xtr[blockIdx.x * 4 + tid] = s;
    }
    __syncthreads();

    // ---- publish via release-atomic (NO per-block L1 flush; release is cumulative
    //      over the preceding __syncthreads, covering the 4 g_xtr stores) ----
    if (tid == 0) {
        int old;
        asm volatile("atom.release.gpu.global.add.s32 %0, [%1], 1;"
                     : "=r"(old) : "l"(&g_done) : "memory");
        s_last = (old == (int)gridDim.x - 1);
    }
    __syncthreads();
    if (!s_last) return;
    asm volatile("fence.acq_rel.gpu;" ::: "memory");   // acquire side, one block only

    // ---- inline router: (bb, m, half) per thread; shfl_xor(1) combines halves ----
    __shared__ float r_logit[16][8];
    {
        int bb = tid >> 4;              // 0..15
        int m  = (tid >> 1) & 7;
        int half = tid & 1;
        const float* xt = g_xtr + bb * DD + half * 256;
        const float* wr = W_r + (half * 256) * 8 + m;
        const float* wn = W_noise + (half * 256) * 8 + m;
        float blin = b_lin[0];
        float p = 0.f, pn = 0.f;
        #pragma unroll 8
        for (int d = 0; d < 256; d++) {
            float v = xt[d] + blin;
            p  = fmaf(v, wr[d * 8], p);
            pn = fmaf(v, wn[d * 8], pn);
        }
        p  += __shfl_xor_sync(0xffffffffu, p, 1);
        pn += __shfl_xor_sync(0xffffffffu, pn, 1);
        if (half == 0) {
            float base = p + b_r[m];
            float nl = pn + b_noise[m];
            float ns = log1pf(expf(-fabsf(nl))) + fmaxf(nl, 0.f);   // softplus
            r_logit[bb][m] = base + noise[bb * 8 + m] * ns;
        }
    }
    __syncthreads();
    if (tid < 128) {
        int bb = tid >> 3, i = tid & 7;
        float lg[8], mx = -FLT_MAX;
        #pragma unroll
        for (int j = 0; j < 8; j++) { lg[j] = r_logit[bb][j]; mx = fmaxf(mx, lg[j]); }
        float es = 0.f;
        #pragma unroll
        for (int j = 0; j < 8; j++) es += expf(lg[j] - mx);
        float pwi = expf(lg[i] - mx) / es;
        int rank = 0;
        #pragma unroll
        for (int j = 0; j < 8; j++)
            if (lg[j] > lg[i] || (lg[j] == lg[i] && j < i)) rank++;
        out[bb * 8 + i] = (rank < 4) ? pwi : 0.f;
    }
    if (tid == 0) g_done = 0;            // reset for next graph replay
}

// ---------------- launch ----------------
extern "C" void kernel_launch(void* const* d_in, const int* in_sizes, int n_in,
                              void* d_out, int out_size) {
    const float* x       = (const float*)d_in[0];
    const float* noise   = (const float*)d_in[1];
    const float* W_r     = (const float*)d_in[2];
    const float* b_r     = (const float*)d_in[3];
    const float* W_noise = (const float*)d_in[4];
    const float* b_noise = (const float*)d_in[5];
    const float* W_trend = (const float*)d_in[6];
    const float* b_trend = (const float*)d_in[7];
    const float* W_lin   = (const float*)d_in[8];
    const float* b_lin   = (const float*)d_in[9];
    float* out = (float*)d_out;

    k_fused<<<BB * DD / 4, 256>>>(x, W_trend, b_trend, W_lin,
                                  noise, W_r, b_r, W_noise, b_noise, b_lin, out);
}